// round 1
// baseline (speedup 1.0000x reference)
#include <cuda_runtime.h>

// HelionGeluD8: fused isotypic->regular butterfly, 8x erf-GeLU, regular->isotypic butterfly.
// B=16, N=1024, C=512. M = B*N = 16384 rows of C floats.
// Inputs (metadata order): x_A1, x_A2, x_B1, x_B2  each (M, C) f32
//                          x_2d (M, 2, 2C) f32  -> rows of 4C floats
// Output buffer: [iso0 | iso1 | iso2 | iso3 | y_2d], each iso (M,C), y_2d (M,4C).

#define SQRT2_OVER_4 0.3535533906f
#define SQRT_OVER_2  0.7071067812f

static __device__ __forceinline__ float gelu_f(float x) {
    return x * (0.5f * (1.0f + erff(SQRT_OVER_2 * x)));
}

// Vectorized: one thread handles one float4 (4 consecutive c) of one row.
// C4 = C/4 = 128 vec4 per row for the A tensors; 4*C4 = 512 vec4 per row of x_2d/y_2d.
__global__ void __launch_bounds__(256) helion_gelu_d8_kernel(
    const float4* __restrict__ xA1,
    const float4* __restrict__ xA2,
    const float4* __restrict__ xB1,
    const float4* __restrict__ xB2,
    const float4* __restrict__ x2d,
    float4* __restrict__ out,
    int total_vec,   // M * C4
    int C4,          // 128
    int MC4)         // M * C4
{
    int tid = blockIdx.x * blockDim.x + threadIdx.x;
    if (tid >= total_vec) return;

    int r  = tid / C4;          // row (b*N+n)
    int c4 = tid - r * C4;      // vec4 column within row

    int base2d = r * (4 * C4) + c4;   // x_2d/y_2d row stride is 4C floats = 4*C4 vec4

    float4 vx0 = xA1[tid];
    float4 vx1 = xA2[tid];
    float4 vx2 = xB1[tid];
    float4 vx3 = xB2[tid];
    float4 vy0 = x2d[base2d];
    float4 vy1 = x2d[base2d + C4];
    float4 vy2 = x2d[base2d + 2 * C4];
    float4 vy3 = x2d[base2d + 3 * C4];

    float4 o0, o1, o2, o3, o4, o5, o6, o7;

    const float* px0 = &vx0.x; const float* px1 = &vx1.x;
    const float* px2 = &vx2.x; const float* px3 = &vx3.x;
    const float* py0 = &vy0.x; const float* py1 = &vy1.x;
    const float* py2 = &vy2.x; const float* py3 = &vy3.x;
    float* po0 = &o0.x; float* po1 = &o1.x; float* po2 = &o2.x; float* po3 = &o3.x;
    float* po4 = &o4.x; float* po5 = &o5.x; float* po6 = &o6.x; float* po7 = &o7.x;

#pragma unroll
    for (int k = 0; k < 4; k++) {
        float x0 = px0[k], x1 = px1[k], x2 = px2[k], x3 = px3[k];
        float y0 = py0[k], y1 = py1[k], y2 = py2[k], y3 = py3[k];

        // isotypic_to_regular
        float a = x0 + x1, b = x0 - x1;
        float c = x2 + x3, d = x2 - x3;
        float e = y0 + y1, f = y0 - y1;
        float g = y2 + y3, h = y2 - y3;
        float apc = a + c, amc = a - c;
        float bpd = b + d, bmd = b - d;
        float eph = e + h, emh = e - h;
        float fpg = f + g, fmg = f - g;

        float r0 = SQRT2_OVER_4 * (apc + eph);
        float r1 = SQRT2_OVER_4 * (amc + fmg);
        float r2 = SQRT2_OVER_4 * (apc - eph);
        float r3 = SQRT2_OVER_4 * (amc - fmg);
        float r4 = SQRT2_OVER_4 * (bpd - fpg);
        float r5 = SQRT2_OVER_4 * (bmd - emh);
        float r6 = SQRT2_OVER_4 * (bpd + fpg);
        float r7 = SQRT2_OVER_4 * (bmd + emh);

        // gelu
        r0 = gelu_f(r0); r1 = gelu_f(r1); r2 = gelu_f(r2); r3 = gelu_f(r3);
        r4 = gelu_f(r4); r5 = gelu_f(r5); r6 = gelu_f(r6); r7 = gelu_f(r7);

        // regular_to_isotypic  (inputs x0..x3 = r0..r3, y0..y3 = r4..r7)
        float a2 = r0 + r1, b2 = r0 - r1;
        float c2 = r2 + r3, d2 = r2 - r3;
        float e2 = r4 + r5, f2 = r4 - r5;
        float g2 = r6 + r7, h2 = r6 - r7;
        float apc2 = a2 + c2, cma2 = c2 - a2;
        float bpd2 = b2 + d2, bmd2 = b2 - d2;
        float epg2 = e2 + g2, gme2 = g2 - e2;
        float fph2 = f2 + h2, fmh2 = f2 - h2;

        po0[k] = SQRT2_OVER_4 * (apc2 + epg2);
        po1[k] = SQRT2_OVER_4 * (apc2 - epg2);
        po2[k] = SQRT2_OVER_4 * (bpd2 + fph2);
        po3[k] = SQRT2_OVER_4 * (bpd2 - fph2);
        po4[k] = SQRT2_OVER_4 * (gme2 - cma2);
        po5[k] = SQRT2_OVER_4 * (bmd2 + fmh2);
        po6[k] = SQRT2_OVER_4 * (bmd2 - fmh2);
        po7[k] = SQRT2_OVER_4 * (gme2 + cma2);
    }

    out[tid]            = o0;
    out[MC4 + tid]      = o1;
    out[2 * MC4 + tid]  = o2;
    out[3 * MC4 + tid]  = o3;
    int ob = 4 * MC4 + base2d;
    out[ob]             = o4;
    out[ob + C4]        = o5;
    out[ob + 2 * C4]    = o6;
    out[ob + 3 * C4]    = o7;
}

extern "C" void kernel_launch(void* const* d_in, const int* in_sizes, int n_in,
                              void* d_out, int out_size) {
    const float4* xA1 = (const float4*)d_in[0];
    const float4* xA2 = (const float4*)d_in[1];
    const float4* xB1 = (const float4*)d_in[2];
    const float4* xB2 = (const float4*)d_in[3];
    const float4* x2d = (const float4*)d_in[4];
    float4* out = (float4*)d_out;

    const int M  = 16 * 1024;      // B * N
    const int C4 = 512 / 4;        // 128
    const int MC4 = M * C4;        // 2,097,152
    const int total_vec = MC4;

    dim3 block(256);
    dim3 grid((total_vec + 255) / 256);
    helion_gelu_d8_kernel<<<grid, block>>>(xA1, xA2, xB1, xB2, x2d, out,
                                           total_vec, C4, MC4);
}

// round 2
// speedup vs baseline: 1.0722x; 1.0722x over previous
#include <cuda_runtime.h>

// HelionGeluD8: fused isotypic->regular butterfly, 8x erf-GeLU, regular->isotypic butterfly.
// B=16, N=1024, C=512. M = B*N = 16384 rows of C floats.
// Inputs: x_A1..x_B2 each (M, C) f32; x_2d (M, 2, 2C) f32.
// Output: [iso0 | iso1 | iso2 | iso3 | y_2d].

#define SQRT2_OVER_4 0.3535533906f
#define SQRT_OVER_2  0.7071067812f

// Abramowitz-Stegun 7.1.26 erf: max abs err 1.5e-7.
// erf(x) = sign(x) * (1 - t*(a1+t*(a2+t*(a3+t*(a4+t*a5)))) * exp(-x^2)),  t=1/(1+p|x|)
static __device__ __forceinline__ float gelu_f(float v) {
    const float p  = 0.3275911f;
    const float a1 = 0.254829592f;
    const float a2 = -0.284496736f;
    const float a3 = 1.421413741f;
    const float a4 = -1.453152027f;
    const float a5 = 1.061405429f;

    float z = SQRT_OVER_2 * v;
    float s = fabsf(z);
    float t = __fdividef(1.0f, fmaf(p, s, 1.0f));      // MUFU.RCP path
    float poly = fmaf(a5, t, a4);
    poly = fmaf(poly, t, a3);
    poly = fmaf(poly, t, a2);
    poly = fmaf(poly, t, a1);
    poly = poly * t;
    float ex = __expf(-s * s);                          // MUFU.EX2 path
    float erf_pos = fmaf(-poly, ex, 1.0f);
    float erfz = copysignf(erf_pos, z);
    float h = 0.5f * v;
    return fmaf(h, erfz, h);                            // v*0.5*(1+erf)
}

__global__ void __launch_bounds__(256) helion_gelu_d8_kernel(
    const float4* __restrict__ xA1,
    const float4* __restrict__ xA2,
    const float4* __restrict__ xB1,
    const float4* __restrict__ xB2,
    const float4* __restrict__ x2d,
    float4* __restrict__ out,
    int total_vec,   // M * C4
    int C4,          // 128
    int MC4)         // M * C4
{
    int tid = blockIdx.x * blockDim.x + threadIdx.x;
    if (tid >= total_vec) return;

    int r  = tid >> 7;           // row (C4 = 128)
    int c4 = tid & 127;

    int base2d = r * (4 * C4) + c4;

    float4 vx0 = xA1[tid];
    float4 vx1 = xA2[tid];
    float4 vx2 = xB1[tid];
    float4 vx3 = xB2[tid];
    float4 vy0 = x2d[base2d];
    float4 vy1 = x2d[base2d + C4];
    float4 vy2 = x2d[base2d + 2 * C4];
    float4 vy3 = x2d[base2d + 3 * C4];

    float4 o0, o1, o2, o3, o4, o5, o6, o7;

    const float* px0 = &vx0.x; const float* px1 = &vx1.x;
    const float* px2 = &vx2.x; const float* px3 = &vx3.x;
    const float* py0 = &vy0.x; const float* py1 = &vy1.x;
    const float* py2 = &vy2.x; const float* py3 = &vy3.x;
    float* po0 = &o0.x; float* po1 = &o1.x; float* po2 = &o2.x; float* po3 = &o3.x;
    float* po4 = &o4.x; float* po5 = &o5.x; float* po6 = &o6.x; float* po7 = &o7.x;

#pragma unroll
    for (int k = 0; k < 4; k++) {
        float x0 = px0[k], x1 = px1[k], x2 = px2[k], x3 = px3[k];
        float y0 = py0[k], y1 = py1[k], y2 = py2[k], y3 = py3[k];

        // isotypic_to_regular
        float a = x0 + x1, b = x0 - x1;
        float c = x2 + x3, d = x2 - x3;
        float e = y0 + y1, f = y0 - y1;
        float g = y2 + y3, h = y2 - y3;
        float apc = a + c, amc = a - c;
        float bpd = b + d, bmd = b - d;
        float eph = e + h, emh = e - h;
        float fpg = f + g, fmg = f - g;

        float r0 = SQRT2_OVER_4 * (apc + eph);
        float r1 = SQRT2_OVER_4 * (amc + fmg);
        float r2 = SQRT2_OVER_4 * (apc - eph);
        float r3 = SQRT2_OVER_4 * (amc - fmg);
        float r4 = SQRT2_OVER_4 * (bpd - fpg);
        float r5 = SQRT2_OVER_4 * (bmd - emh);
        float r6 = SQRT2_OVER_4 * (bpd + fpg);
        float r7 = SQRT2_OVER_4 * (bmd + emh);

        // gelu
        r0 = gelu_f(r0); r1 = gelu_f(r1); r2 = gelu_f(r2); r3 = gelu_f(r3);
        r4 = gelu_f(r4); r5 = gelu_f(r5); r6 = gelu_f(r6); r7 = gelu_f(r7);

        // regular_to_isotypic
        float a2 = r0 + r1, b2 = r0 - r1;
        float c2 = r2 + r3, d2 = r2 - r3;
        float e2 = r4 + r5, f2 = r4 - r5;
        float g2 = r6 + r7, h2 = r6 - r7;
        float apc2 = a2 + c2, cma2 = c2 - a2;
        float bpd2 = b2 + d2, bmd2 = b2 - d2;
        float epg2 = e2 + g2, gme2 = g2 - e2;
        float fph2 = f2 + h2, fmh2 = f2 - h2;

        po0[k] = SQRT2_OVER_4 * (apc2 + epg2);
        po1[k] = SQRT2_OVER_4 * (apc2 - epg2);
        po2[k] = SQRT2_OVER_4 * (bpd2 + fph2);
        po3[k] = SQRT2_OVER_4 * (bpd2 - fph2);
        po4[k] = SQRT2_OVER_4 * (gme2 - cma2);
        po5[k] = SQRT2_OVER_4 * (bmd2 + fmh2);
        po6[k] = SQRT2_OVER_4 * (bmd2 - fmh2);
        po7[k] = SQRT2_OVER_4 * (gme2 + cma2);
    }

    out[tid]            = o0;
    out[MC4 + tid]      = o1;
    out[2 * MC4 + tid]  = o2;
    out[3 * MC4 + tid]  = o3;
    int ob = 4 * MC4 + base2d;
    out[ob]             = o4;
    out[ob + C4]        = o5;
    out[ob + 2 * C4]    = o6;
    out[ob + 3 * C4]    = o7;
}

extern "C" void kernel_launch(void* const* d_in, const int* in_sizes, int n_in,
                              void* d_out, int out_size) {
    const float4* xA1 = (const float4*)d_in[0];
    const float4* xA2 = (const float4*)d_in[1];
    const float4* xB1 = (const float4*)d_in[2];
    const float4* xB2 = (const float4*)d_in[3];
    const float4* x2d = (const float4*)d_in[4];
    float4* out = (float4*)d_out;

    const int M  = 16 * 1024;
    const int C4 = 512 / 4;
    const int MC4 = M * C4;
    const int total_vec = MC4;

    dim3 block(256);
    dim3 grid((total_vec + 255) / 256);
    helion_gelu_d8_kernel<<<grid, block>>>(xA1, xA2, xB1, xB2, x2d, out,
                                           total_vec, C4, MC4);
}